// round 4
// baseline (speedup 1.0000x reference)
#include <cuda_runtime.h>
#include <cuda_fp16.h>

// ---------------------------------------------------------------------------
// BUIR / LightGCN forward, fp16-fused, rank-sort CSR version.
//   - Online+target embeddings interleaved per node: H[r] = [64 on | 64 tg]
//     fp16 = 256B row. One SpMM pass computes BOTH encodings' layers.
//   - CSR by counting sort; hist captures each edge's within-row rank so the
//     scatter needs NO atomics (pos = rowptr[row] + rank).
//   - SpMM: warp per row, fixed fully-unrolled 16 pair-steps per 32-edge
//     block (pad edges have v=0 -> exact; pad gathers hit node 0, L1-hot).
//   - Layer 3 only at sampled rows, fused with acc=(ego+X1+X2+X3)/4.
// Output layout: [u_pred | u_target | i_pred | i_target], each [B,64] f32.
// ---------------------------------------------------------------------------

#define D        64
#define HROW     64          // half2 per node row (128 halfs = 256B)
#define N_NODES  300000
#define NNZ_MAX  6400000
#define B_MAX    4096
#define HIST_BLOCKS 1024

// Scratch (device globals — no allocation allowed in kernel_launch)
__device__ int     g_counts[N_NODES];        // zero at load; re-zeroed each call
__device__ int     g_rowptr[N_NODES + 1];
__device__ int     g_rank[NNZ_MAX];          // per-edge within-row rank
__device__ int     g_bsums[512];
__device__ int2    g_edges[NNZ_MAX];         // {col, val bits}, row-sorted
__device__ __half2 g_H0[(size_t)N_NODES * HROW];
__device__ __half2 g_H1[(size_t)N_NODES * HROW];
__device__ __half2 g_H2[(size_t)N_NODES * HROW];
__device__ float   g_S[(size_t)2 * B_MAX * D];

static __device__ __forceinline__ unsigned h2_as_u(__half2 h) {
    return *reinterpret_cast<unsigned*>(&h);
}
static __device__ __forceinline__ __half2 u_as_h2(unsigned u) {
    return *reinterpret_cast<__half2*>(&u);
}

// ---------------------------------------------------------------------------
// Fused: histogram+rank (blocks [0,HIST_BLOCKS)) + ego->fp16 convert (rest)
// ---------------------------------------------------------------------------
__global__ void __launch_bounds__(256) hist_convert_kernel(
    const int* __restrict__ row, int nnz,
    int* __restrict__ counts, int* __restrict__ rank,
    const float2* __restrict__ ue_on, const float2* __restrict__ ie_on,
    const float2* __restrict__ ue_tg, const float2* __restrict__ ie_tg,
    __half2* __restrict__ h0, int n, int usplit)
{
    if (blockIdx.x < HIST_BLOCKS) {
        int nq = nnz >> 2;                               // int4 chunks
        const int4* row4 = (const int4*)row;
        for (int i = blockIdx.x * 256 + threadIdx.x; i < nq;
             i += HIST_BLOCKS * 256) {
            int4 r = __ldcs(&row4[i]);
            int4 k;
            k.x = atomicAdd(&counts[r.x], 1);
            k.y = atomicAdd(&counts[r.y], 1);
            k.z = atomicAdd(&counts[r.z], 1);
            k.w = atomicAdd(&counts[r.w], 1);
            __stcs(&((int4*)rank)[i], k);
        }
        // tail (nnz not multiple of 4)
        int t = nq * 4 + blockIdx.x * 256 + threadIdx.x;
        if (t < nnz)
            rank[t] = atomicAdd(&counts[__ldcs(&row[t])], 1);
    } else {
        int idx = (blockIdx.x - HIST_BLOCKS) * 256 + threadIdx.x;
        if (idx >= n * 32) return;
        int r = idx >> 5;
        int k = idx & 31;
        float2 on, tg;
        if (r < usplit) {
            on = ue_on[(size_t)r * 32 + k];
            tg = ue_tg[(size_t)r * 32 + k];
        } else {
            on = ie_on[(size_t)(r - usplit) * 32 + k];
            tg = ie_tg[(size_t)(r - usplit) * 32 + k];
        }
        h0[(size_t)r * HROW + k]      = __floats2half2_rn(on.x, on.y);
        h0[(size_t)r * HROW + 32 + k] = __floats2half2_rn(tg.x, tg.y);
    }
}

// ---------------------------------------------------------------------------
// CSR scans / scatter
// ---------------------------------------------------------------------------
__global__ void scan_block_kernel(const int* __restrict__ counts, int n,
                                  int* __restrict__ excl, int* __restrict__ bsums) {
    __shared__ int sd[1024];
    int tid = threadIdx.x;
    int i = blockIdx.x * 1024 + tid;
    int v = (i < n) ? counts[i] : 0;
    sd[tid] = v;
    __syncthreads();
    #pragma unroll
    for (int off = 1; off < 1024; off <<= 1) {
        int t = (tid >= off) ? sd[tid - off] : 0;
        __syncthreads();
        sd[tid] += t;
        __syncthreads();
    }
    if (i < n) excl[i] = sd[tid] - v;
    if (tid == 1023) bsums[blockIdx.x] = sd[1023];
}

__global__ void scan_top_kernel(int* __restrict__ bsums, int nb) {
    __shared__ int sd[512];
    int tid = threadIdx.x;
    int v = (tid < nb) ? bsums[tid] : 0;
    sd[tid] = v;
    __syncthreads();
    #pragma unroll
    for (int off = 1; off < 512; off <<= 1) {
        int t = (tid >= off) ? sd[tid - off] : 0;
        __syncthreads();
        sd[tid] += t;
        __syncthreads();
    }
    if (tid < nb) bsums[tid] = sd[tid] - v;
}

// Finalizes rowptr; re-zeroes counts for the NEXT call.
__global__ void scan_add_kernel(int* __restrict__ rowptr, int* __restrict__ counts,
                                const int* __restrict__ bsums, int n, int nnz) {
    int i = blockIdx.x * 1024 + threadIdx.x;
    if (i < n) {
        rowptr[i] += bsums[blockIdx.x];
        counts[i] = 0;
    }
    if (i == 0) rowptr[n] = nnz;
}

// Atomic-free scatter: pos = rowptr[row] + rank.
__global__ void scatter_kernel(const int* __restrict__ row, const int* __restrict__ col,
                               const float* __restrict__ val,
                               const int* __restrict__ rank, int nnz,
                               const int* __restrict__ rowptr, int2* __restrict__ edges) {
    for (int i = blockIdx.x * blockDim.x + threadIdx.x; i < nnz;
         i += gridDim.x * blockDim.x) {
        int r = __ldcs(&row[i]);
        int pos = __ldg(&rowptr[r]) + __ldcs(&rank[i]);
        __stcs(&edges[pos], make_int2(__ldcs(&col[i]),
                                      __float_as_int(__ldcs(&val[i]))));
    }
}

// ---------------------------------------------------------------------------
// Fused SpMM: warp per row. Fixed fully-unrolled 16 pair-steps per 32-edge
// block. Pad lanes carry ev=(0,0): v=0 makes the FMA exact, and the pad
// gather hits node 0's row (L1-hot, never reaches LTS).
// ---------------------------------------------------------------------------
__global__ void __launch_bounds__(256) spmm_fused_kernel(
    const int* __restrict__ rowptr, const int2* __restrict__ edges,
    const __half2* __restrict__ xin, __half2* __restrict__ xout, int nrows)
{
    int w = (blockIdx.x * 256 + threadIdx.x) >> 5;
    if (w >= nrows) return;
    int lane = threadIdx.x & 31;
    int half = lane >> 4;          // which edge of the pair
    int hl   = lane & 15;          // 16B segment index within the row
    int start = __ldg(&rowptr[w]);
    int end   = __ldg(&rowptr[w + 1]);

    float2 acc[4];
    #pragma unroll
    for (int k = 0; k < 4; k++) acc[k] = make_float2(0.f, 0.f);

    const char* xbase = (const char*)xin;

    for (int base = start; base < end; base += 32) {
        int2 ev = make_int2(0, 0);                 // pad: col 0 / val 0
        if (base + lane < end) ev = __ldcs(&edges[base + lane]);
        #pragma unroll
        for (int jj = 0; jj < 16; jj++) {
            int src = 2 * jj + half;
            int   c = __shfl_sync(0xffffffffu, ev.x, src);
            float v = __int_as_float(__shfl_sync(0xffffffffu, ev.y, src));
            uint4 raw = __ldg((const uint4*)(xbase + (size_t)c * 256 + hl * 16));
            float2 f0 = __half22float2(u_as_h2(raw.x));
            float2 f1 = __half22float2(u_as_h2(raw.y));
            float2 f2 = __half22float2(u_as_h2(raw.z));
            float2 f3 = __half22float2(u_as_h2(raw.w));
            acc[0].x = fmaf(v, f0.x, acc[0].x);
            acc[0].y = fmaf(v, f0.y, acc[0].y);
            acc[1].x = fmaf(v, f1.x, acc[1].x);
            acc[1].y = fmaf(v, f1.y, acc[1].y);
            acc[2].x = fmaf(v, f2.x, acc[2].x);
            acc[2].y = fmaf(v, f2.y, acc[2].y);
            acc[3].x = fmaf(v, f3.x, acc[3].x);
            acc[3].y = fmaf(v, f3.y, acc[3].y);
        }
    }

    #pragma unroll
    for (int k = 0; k < 4; k++) {
        acc[k].x += __shfl_xor_sync(0xffffffffu, acc[k].x, 16);
        acc[k].y += __shfl_xor_sync(0xffffffffu, acc[k].y, 16);
    }
    if (lane < 16) {
        uint4 o;
        o.x = h2_as_u(__floats2half2_rn(acc[0].x, acc[0].y));
        o.y = h2_as_u(__floats2half2_rn(acc[1].x, acc[1].y));
        o.z = h2_as_u(__floats2half2_rn(acc[2].x, acc[2].y));
        o.w = h2_as_u(__floats2half2_rn(acc[3].x, acc[3].y));
        __stcs((uint4*)((char*)xout + (size_t)w * 256 + hl * 16), o);
    }
}

// ---------------------------------------------------------------------------
// Layer-3 at sampled rows (both encodings), fused with
// acc = 0.25*(ego_fp32 + X1 + X2 + X3). Online acc -> S, target acc -> out.
// ---------------------------------------------------------------------------
__global__ void __launch_bounds__(256) sampled_fused_kernel(
    const int* __restrict__ rowptr, const int2* __restrict__ edges,
    const __half2* __restrict__ h1, const __half2* __restrict__ h2,
    const float2* __restrict__ ue_on, const float2* __restrict__ ie_on,
    const float2* __restrict__ ue_tg, const float2* __restrict__ ie_tg,
    const int* __restrict__ user_idx, const int* __restrict__ item_idx,
    float2* __restrict__ s_on,
    float2* __restrict__ out_utg, float2* __restrict__ out_itg,
    int b, int usplit)
{
    int s = (blockIdx.x * 256 + threadIdx.x) >> 5;
    if (s >= 2 * b) return;
    int lane = threadIdx.x & 31;
    int r = (s < b) ? __ldg(&user_idx[s]) : usplit + __ldg(&item_idx[s - b]);

    int start = __ldg(&rowptr[r]);
    int end   = __ldg(&rowptr[r + 1]);
    float2 aon = make_float2(0.f, 0.f);
    float2 atg = make_float2(0.f, 0.f);
    for (int base = start; base < end; base += 32) {
        int2 ev = make_int2(0, 0);
        if (base + lane < end) ev = edges[base + lane];
        #pragma unroll
        for (int j = 0; j < 32; j++) {
            int   c = __shfl_sync(0xffffffffu, ev.x, j);
            float v = __int_as_float(__shfl_sync(0xffffffffu, ev.y, j));
            const __half2* src = h2 + (size_t)c * HROW;
            float2 a = __half22float2(__ldg(src + lane));
            float2 t = __half22float2(__ldg(src + 32 + lane));
            aon.x = fmaf(v, a.x, aon.x);
            aon.y = fmaf(v, a.y, aon.y);
            atg.x = fmaf(v, t.x, atg.x);
            atg.y = fmaf(v, t.y, atg.y);
        }
    }

    float2 e_on = (r < usplit) ? __ldg(&ue_on[(size_t)r * 32 + lane])
                               : __ldg(&ie_on[(size_t)(r - usplit) * 32 + lane]);
    float2 e_tg = (r < usplit) ? __ldg(&ue_tg[(size_t)r * 32 + lane])
                               : __ldg(&ie_tg[(size_t)(r - usplit) * 32 + lane]);
    float2 x1on = __half22float2(__ldg(h1 + (size_t)r * HROW + lane));
    float2 x1tg = __half22float2(__ldg(h1 + (size_t)r * HROW + 32 + lane));
    float2 x2on = __half22float2(__ldg(h2 + (size_t)r * HROW + lane));
    float2 x2tg = __half22float2(__ldg(h2 + (size_t)r * HROW + 32 + lane));

    float2 ron, rtg;
    ron.x = 0.25f * (e_on.x + x1on.x + x2on.x + aon.x);
    ron.y = 0.25f * (e_on.y + x1on.y + x2on.y + aon.y);
    rtg.x = 0.25f * (e_tg.x + x1tg.x + x2tg.x + atg.x);
    rtg.y = 0.25f * (e_tg.y + x1tg.y + x2tg.y + atg.y);

    s_on[(size_t)s * 32 + lane] = ron;
    float2* dtg = (s < b) ? (out_utg + (size_t)s * 32 + lane)
                          : (out_itg + (size_t)(s - b) * 32 + lane);
    *dtg = rtg;
}

// ---------------------------------------------------------------------------
// Linear head: out = S @ W^T + bias   (S: [2B,64], W: [64,64] row-major)
// ---------------------------------------------------------------------------
__global__ void __launch_bounds__(256) pred_kernel(
    const float* __restrict__ S, const float* __restrict__ W,
    const float* __restrict__ bias,
    float* __restrict__ out_u, float* __restrict__ out_i, int b)
{
    __shared__ float Wt[64][65];
    __shared__ float srow[4][64];
    __shared__ float sb[64];
    int tx = threadIdx.x, ty = threadIdx.y;
    int tid = ty * 64 + tx;
    for (int idx = tid; idx < 4096; idx += 256)
        Wt[idx & 63][idx >> 6] = W[idx];
    if (tid < 64) sb[tid] = bias[tid];
    int s = blockIdx.x * 4 + ty;
    srow[ty][tx] = S[(size_t)s * 64 + tx];
    __syncthreads();

    float acc = sb[tx];
    #pragma unroll
    for (int k = 0; k < 64; k++)
        acc = fmaf(srow[ty][k], Wt[k][tx], acc);

    float* d = (s < b) ? (out_u + (size_t)s * 64 + tx)
                       : (out_i + (size_t)(s - b) * 64 + tx);
    *d = acc;
}

// ---------------------------------------------------------------------------
// Launch
// ---------------------------------------------------------------------------
extern "C" void kernel_launch(void* const* d_in, const int* in_sizes, int n_in,
                              void* d_out, int out_size) {
    const float* ue_on   = (const float*)d_in[0];
    const float* ie_on   = (const float*)d_in[1];
    const float* ue_tg   = (const float*)d_in[2];
    const float* ie_tg   = (const float*)d_in[3];
    const float* adj_val = (const float*)d_in[4];
    const float* pred_w  = (const float*)d_in[5];
    const float* pred_b  = (const float*)d_in[6];
    const int*   adj_row = (const int*)d_in[7];
    const int*   adj_col = (const int*)d_in[8];
    const int*   user_idx = (const int*)d_in[9];
    const int*   item_idx = (const int*)d_in[10];

    int uN  = in_sizes[0] / D;
    int iN  = in_sizes[1] / D;
    int n   = uN + iN;
    int nnz = in_sizes[4];
    int b   = in_sizes[9];

    int *counts, *rowptr, *rank, *bsums;
    int2* edges;
    __half2 *h0, *h1, *h2;
    float* S;
    cudaGetSymbolAddress((void**)&counts, g_counts);
    cudaGetSymbolAddress((void**)&rowptr, g_rowptr);
    cudaGetSymbolAddress((void**)&rank,   g_rank);
    cudaGetSymbolAddress((void**)&bsums,  g_bsums);
    cudaGetSymbolAddress((void**)&edges,  g_edges);
    cudaGetSymbolAddress((void**)&h0,     g_H0);
    cudaGetSymbolAddress((void**)&h1,     g_H1);
    cudaGetSymbolAddress((void**)&h2,     g_H2);
    cudaGetSymbolAddress((void**)&S,      g_S);

    // --- CSR build (counts pre-zeroed by previous call / module load) ---
    int conv_blocks = (n * 32 + 255) / 256;
    hist_convert_kernel<<<HIST_BLOCKS + conv_blocks, 256>>>(
        adj_row, nnz, counts, rank,
        (const float2*)ue_on, (const float2*)ie_on,
        (const float2*)ue_tg, (const float2*)ie_tg, h0, n, uN);
    int nb = (n + 1023) / 1024;
    scan_block_kernel<<<nb, 1024>>>(counts, n, rowptr, bsums);
    scan_top_kernel<<<1, 512>>>(bsums, nb);
    scan_add_kernel<<<nb, 1024>>>(rowptr, counts, bsums, n, nnz);
    scatter_kernel<<<2048, 256>>>(adj_row, adj_col, adj_val, rank, nnz,
                                  rowptr, edges);

    int spmm_blocks = (n + 7) / 8;
    int samp_blocks = (2 * b + 7) / 8;
    float* out = (float*)d_out;
    size_t BD = (size_t)b * D;

    spmm_fused_kernel<<<spmm_blocks, 256>>>(rowptr, edges, h0, h1, n);
    spmm_fused_kernel<<<spmm_blocks, 256>>>(rowptr, edges, h1, h2, n);
    sampled_fused_kernel<<<samp_blocks, 256>>>(rowptr, edges, h1, h2,
        (const float2*)ue_on, (const float2*)ie_on,
        (const float2*)ue_tg, (const float2*)ie_tg,
        user_idx, item_idx,
        (float2*)S,
        (float2*)(out + BD),
        (float2*)(out + 3 * BD),
        b, uN);
    pred_kernel<<<(2 * b) / 4, dim3(64, 4)>>>(S, pred_w, pred_b,
        out, out + 2 * BD, b);
}

// round 5
// speedup vs baseline: 1.0011x; 1.0011x over previous
#include <cuda_runtime.h>
#include <cuda_fp16.h>

// ---------------------------------------------------------------------------
// BUIR / LightGCN forward, fp16-fused, uint4-gather, 1-kernel-scan version.
//   - Online+target embeddings interleaved per node: H[r] = [64 on | 64 tg]
//     fp16 = 256B row. One SpMM pass computes BOTH encodings' layers.
//   - CSR by counting sort. Scan is ONE kernel: each block gets its base via
//     arrival-order atomicAdd (row ranges need not be ordered across rows).
//   - Hist uses fire-and-forget atomics (REDG); scatter positions via cursor
//     atomics (as in the 575us round-3 version).
//   - SpMM: warp per row, 2 edges per step (half-warp each), one LDG.128 per
//     lane covering 16B of the row; dynamic trip count, unroll 8 for MLP.
//   - Layer 3 only at sampled rows, fused with acc=(ego+X1+X2+X3)/4.
// Output layout: [u_pred | u_target | i_pred | i_target], each [B,64] f32.
// ---------------------------------------------------------------------------

#define D        64
#define HROW     64          // half2 per node row (128 halfs = 256B)
#define N_NODES  300000
#define NNZ_MAX  6400000
#define B_MAX    4096
#define HIST_BLOCKS 1024

// Scratch (device globals — no allocation allowed in kernel_launch)
__device__ int     g_counts[N_NODES];        // zero at load; re-zeroed each call
__device__ int2    g_rowrange[N_NODES];      // {start, end} per row
__device__ int     g_cursor[N_NODES];
__device__ int     g_scan_cursor;            // reset by hist kernel each call
__device__ int2    g_edges[NNZ_MAX];         // {col, val bits}, row-grouped
__device__ __half2 g_H0[(size_t)N_NODES * HROW];
__device__ __half2 g_H1[(size_t)N_NODES * HROW];
__device__ __half2 g_H2[(size_t)N_NODES * HROW];
__device__ float   g_S[(size_t)2 * B_MAX * D];

static __device__ __forceinline__ unsigned h2_as_u(__half2 h) {
    return *reinterpret_cast<unsigned*>(&h);
}
static __device__ __forceinline__ __half2 u_as_h2(unsigned u) {
    return *reinterpret_cast<__half2*>(&u);
}

// ---------------------------------------------------------------------------
// Fused: histogram (blocks [0,HIST_BLOCKS)) + ego->fp16 convert (rest).
// Also resets the scan cursor for the next launch.
// ---------------------------------------------------------------------------
__global__ void __launch_bounds__(256) hist_convert_kernel(
    const int* __restrict__ row, int nnz, int* __restrict__ counts,
    const float2* __restrict__ ue_on, const float2* __restrict__ ie_on,
    const float2* __restrict__ ue_tg, const float2* __restrict__ ie_tg,
    __half2* __restrict__ h0, int n, int usplit)
{
    if (blockIdx.x == 0 && threadIdx.x == 0) g_scan_cursor = 0;
    if (blockIdx.x < HIST_BLOCKS) {
        for (int i = blockIdx.x * 256 + threadIdx.x; i < nnz;
             i += HIST_BLOCKS * 256)
            atomicAdd(&counts[__ldcs(&row[i])], 1);   // return unused -> REDG
    } else {
        int idx = (blockIdx.x - HIST_BLOCKS) * 256 + threadIdx.x;
        if (idx >= n * 32) return;
        int r = idx >> 5;
        int k = idx & 31;
        float2 on, tg;
        if (r < usplit) {
            on = ue_on[(size_t)r * 32 + k];
            tg = ue_tg[(size_t)r * 32 + k];
        } else {
            on = ie_on[(size_t)(r - usplit) * 32 + k];
            tg = ie_tg[(size_t)(r - usplit) * 32 + k];
        }
        h0[(size_t)r * HROW + k]      = __floats2half2_rn(on.x, on.y);
        h0[(size_t)r * HROW + 32 + k] = __floats2half2_rn(tg.x, tg.y);
    }
}

// ---------------------------------------------------------------------------
// Single-kernel scan: block-local inclusive scan; block base claimed by
// arrival-order atomicAdd (valid because CSR ranges need not be row-ordered).
// Emits rowrange + cursor, re-zeroes counts for the next call.
// ---------------------------------------------------------------------------
__global__ void scan_fused_kernel(int* __restrict__ counts, int n,
                                  int2* __restrict__ rowrange,
                                  int* __restrict__ cursor) {
    __shared__ int sd[1024];
    __shared__ int sbase;
    int tid = threadIdx.x;
    int i = blockIdx.x * 1024 + tid;
    int v = (i < n) ? counts[i] : 0;
    sd[tid] = v;
    __syncthreads();
    #pragma unroll
    for (int off = 1; off < 1024; off <<= 1) {
        int t = (tid >= off) ? sd[tid - off] : 0;
        __syncthreads();
        sd[tid] += t;
        __syncthreads();
    }
    if (tid == 1023) sbase = atomicAdd(&g_scan_cursor, sd[1023]);
    __syncthreads();
    if (i < n) {
        int start = sbase + sd[tid] - v;
        rowrange[i] = make_int2(start, start + v);
        cursor[i]   = start;
        counts[i]   = 0;
    }
}

// ---------------------------------------------------------------------------
// Scatter: position via per-row cursor atomics.
// ---------------------------------------------------------------------------
__global__ void scatter_kernel(const int* __restrict__ row, const int* __restrict__ col,
                               const float* __restrict__ val, int nnz,
                               int* __restrict__ cursor, int2* __restrict__ edges) {
    for (int i = blockIdx.x * blockDim.x + threadIdx.x; i < nnz;
         i += gridDim.x * blockDim.x) {
        int r = __ldcs(&row[i]);
        int pos = atomicAdd(&cursor[r], 1);
        __stcs(&edges[pos], make_int2(__ldcs(&col[i]),
                                      __float_as_int(__ldcs(&val[i]))));
    }
}

// ---------------------------------------------------------------------------
// Fused SpMM: warp per row. 2 edges per step (half-warp 0 -> edge j,
// half-warp 1 -> edge j+1). Each lane: one LDG.128 covering 16B of the 256B
// node row. Partials combined with shfl_xor(16); lanes 0-15 store uint4.
// ---------------------------------------------------------------------------
__global__ void __launch_bounds__(256) spmm_fused_kernel(
    const int2* __restrict__ rowrange, const int2* __restrict__ edges,
    const __half2* __restrict__ xin, __half2* __restrict__ xout, int nrows)
{
    int w = (blockIdx.x * 256 + threadIdx.x) >> 5;
    if (w >= nrows) return;
    int lane = threadIdx.x & 31;
    int half = lane >> 4;          // which edge of the pair
    int hl   = lane & 15;          // 16B segment index within the row
    int2 rr = __ldg(&rowrange[w]);
    int start = rr.x;
    int end   = rr.y;

    float2 acc[4];
    #pragma unroll
    for (int k = 0; k < 4; k++) acc[k] = make_float2(0.f, 0.f);

    const char* xbase = (const char*)xin;

    for (int base = start; base < end; base += 32) {
        int2 ev = make_int2(0, 0);                 // pad: col 0 / val 0
        if (base + lane < end) ev = __ldcs(&edges[base + lane]);
        int cnt = min(32, end - base);
        #pragma unroll 8
        for (int j = 0; j < cnt; j += 2) {
            int src = j + half;                    // half 1 reads pad if j+1>=cnt
            int   c = __shfl_sync(0xffffffffu, ev.x, src);
            float v = __int_as_float(__shfl_sync(0xffffffffu, ev.y, src));
            uint4 raw = __ldg((const uint4*)(xbase + (size_t)c * 256 + hl * 16));
            float2 f0 = __half22float2(u_as_h2(raw.x));
            float2 f1 = __half22float2(u_as_h2(raw.y));
            float2 f2 = __half22float2(u_as_h2(raw.z));
            float2 f3 = __half22float2(u_as_h2(raw.w));
            acc[0].x = fmaf(v, f0.x, acc[0].x);
            acc[0].y = fmaf(v, f0.y, acc[0].y);
            acc[1].x = fmaf(v, f1.x, acc[1].x);
            acc[1].y = fmaf(v, f1.y, acc[1].y);
            acc[2].x = fmaf(v, f2.x, acc[2].x);
            acc[2].y = fmaf(v, f2.y, acc[2].y);
            acc[3].x = fmaf(v, f3.x, acc[3].x);
            acc[3].y = fmaf(v, f3.y, acc[3].y);
        }
    }

    #pragma unroll
    for (int k = 0; k < 4; k++) {
        acc[k].x += __shfl_xor_sync(0xffffffffu, acc[k].x, 16);
        acc[k].y += __shfl_xor_sync(0xffffffffu, acc[k].y, 16);
    }
    if (lane < 16) {
        uint4 o;
        o.x = h2_as_u(__floats2half2_rn(acc[0].x, acc[0].y));
        o.y = h2_as_u(__floats2half2_rn(acc[1].x, acc[1].y));
        o.z = h2_as_u(__floats2half2_rn(acc[2].x, acc[2].y));
        o.w = h2_as_u(__floats2half2_rn(acc[3].x, acc[3].y));
        __stcs((uint4*)((char*)xout + (size_t)w * 256 + hl * 16), o);
    }
}

// ---------------------------------------------------------------------------
// Layer-3 at sampled rows (both encodings), fused with
// acc = 0.25*(ego_fp32 + X1 + X2 + X3). Online acc -> S, target acc -> out.
// ---------------------------------------------------------------------------
__global__ void __launch_bounds__(256) sampled_fused_kernel(
    const int2* __restrict__ rowrange, const int2* __restrict__ edges,
    const __half2* __restrict__ h1, const __half2* __restrict__ h2,
    const float2* __restrict__ ue_on, const float2* __restrict__ ie_on,
    const float2* __restrict__ ue_tg, const float2* __restrict__ ie_tg,
    const int* __restrict__ user_idx, const int* __restrict__ item_idx,
    float2* __restrict__ s_on,
    float2* __restrict__ out_utg, float2* __restrict__ out_itg,
    int b, int usplit)
{
    int s = (blockIdx.x * 256 + threadIdx.x) >> 5;
    if (s >= 2 * b) return;
    int lane = threadIdx.x & 31;
    int r = (s < b) ? __ldg(&user_idx[s]) : usplit + __ldg(&item_idx[s - b]);

    int2 rr = __ldg(&rowrange[r]);
    int start = rr.x;
    int end   = rr.y;
    float2 aon = make_float2(0.f, 0.f);
    float2 atg = make_float2(0.f, 0.f);
    for (int base = start; base < end; base += 32) {
        int2 ev = make_int2(0, 0);
        if (base + lane < end) ev = edges[base + lane];
        int cnt = min(32, end - base);
        #pragma unroll 4
        for (int j = 0; j < cnt; j++) {
            int   c = __shfl_sync(0xffffffffu, ev.x, j);
            float v = __int_as_float(__shfl_sync(0xffffffffu, ev.y, j));
            const __half2* src = h2 + (size_t)c * HROW;
            float2 a = __half22float2(__ldg(src + lane));
            float2 t = __half22float2(__ldg(src + 32 + lane));
            aon.x = fmaf(v, a.x, aon.x);
            aon.y = fmaf(v, a.y, aon.y);
            atg.x = fmaf(v, t.x, atg.x);
            atg.y = fmaf(v, t.y, atg.y);
        }
    }

    float2 e_on = (r < usplit) ? __ldg(&ue_on[(size_t)r * 32 + lane])
                               : __ldg(&ie_on[(size_t)(r - usplit) * 32 + lane]);
    float2 e_tg = (r < usplit) ? __ldg(&ue_tg[(size_t)r * 32 + lane])
                               : __ldg(&ie_tg[(size_t)(r - usplit) * 32 + lane]);
    float2 x1on = __half22float2(__ldg(h1 + (size_t)r * HROW + lane));
    float2 x1tg = __half22float2(__ldg(h1 + (size_t)r * HROW + 32 + lane));
    float2 x2on = __half22float2(__ldg(h2 + (size_t)r * HROW + lane));
    float2 x2tg = __half22float2(__ldg(h2 + (size_t)r * HROW + 32 + lane));

    float2 ron, rtg;
    ron.x = 0.25f * (e_on.x + x1on.x + x2on.x + aon.x);
    ron.y = 0.25f * (e_on.y + x1on.y + x2on.y + aon.y);
    rtg.x = 0.25f * (e_tg.x + x1tg.x + x2tg.x + atg.x);
    rtg.y = 0.25f * (e_tg.y + x1tg.y + x2tg.y + atg.y);

    s_on[(size_t)s * 32 + lane] = ron;
    float2* dtg = (s < b) ? (out_utg + (size_t)s * 32 + lane)
                          : (out_itg + (size_t)(s - b) * 32 + lane);
    *dtg = rtg;
}

// ---------------------------------------------------------------------------
// Linear head: out = S @ W^T + bias   (S: [2B,64], W: [64,64] row-major)
// ---------------------------------------------------------------------------
__global__ void __launch_bounds__(256) pred_kernel(
    const float* __restrict__ S, const float* __restrict__ W,
    const float* __restrict__ bias,
    float* __restrict__ out_u, float* __restrict__ out_i, int b)
{
    __shared__ float Wt[64][65];
    __shared__ float srow[4][64];
    __shared__ float sb[64];
    int tx = threadIdx.x, ty = threadIdx.y;
    int tid = ty * 64 + tx;
    for (int idx = tid; idx < 4096; idx += 256)
        Wt[idx & 63][idx >> 6] = W[idx];
    if (tid < 64) sb[tid] = bias[tid];
    int s = blockIdx.x * 4 + ty;
    srow[ty][tx] = S[(size_t)s * 64 + tx];
    __syncthreads();

    float acc = sb[tx];
    #pragma unroll
    for (int k = 0; k < 64; k++)
        acc = fmaf(srow[ty][k], Wt[k][tx], acc);

    float* d = (s < b) ? (out_u + (size_t)s * 64 + tx)
                       : (out_i + (size_t)(s - b) * 64 + tx);
    *d = acc;
}

// ---------------------------------------------------------------------------
// Launch
// ---------------------------------------------------------------------------
extern "C" void kernel_launch(void* const* d_in, const int* in_sizes, int n_in,
                              void* d_out, int out_size) {
    const float* ue_on   = (const float*)d_in[0];
    const float* ie_on   = (const float*)d_in[1];
    const float* ue_tg   = (const float*)d_in[2];
    const float* ie_tg   = (const float*)d_in[3];
    const float* adj_val = (const float*)d_in[4];
    const float* pred_w  = (const float*)d_in[5];
    const float* pred_b  = (const float*)d_in[6];
    const int*   adj_row = (const int*)d_in[7];
    const int*   adj_col = (const int*)d_in[8];
    const int*   user_idx = (const int*)d_in[9];
    const int*   item_idx = (const int*)d_in[10];

    int uN  = in_sizes[0] / D;
    int iN  = in_sizes[1] / D;
    int n   = uN + iN;
    int nnz = in_sizes[4];
    int b   = in_sizes[9];

    int *counts, *cursor;
    int2 *rowrange, *edges;
    __half2 *h0, *h1, *h2;
    float* S;
    cudaGetSymbolAddress((void**)&counts,   g_counts);
    cudaGetSymbolAddress((void**)&rowrange, g_rowrange);
    cudaGetSymbolAddress((void**)&cursor,   g_cursor);
    cudaGetSymbolAddress((void**)&edges,    g_edges);
    cudaGetSymbolAddress((void**)&h0,       g_H0);
    cudaGetSymbolAddress((void**)&h1,       g_H1);
    cudaGetSymbolAddress((void**)&h2,       g_H2);
    cudaGetSymbolAddress((void**)&S,        g_S);

    // --- CSR build (counts pre-zeroed by previous call / module load) ---
    int conv_blocks = (n * 32 + 255) / 256;
    hist_convert_kernel<<<HIST_BLOCKS + conv_blocks, 256>>>(
        adj_row, nnz, counts,
        (const float2*)ue_on, (const float2*)ie_on,
        (const float2*)ue_tg, (const float2*)ie_tg, h0, n, uN);
    int nb = (n + 1023) / 1024;
    scan_fused_kernel<<<nb, 1024>>>(counts, n, rowrange, cursor);
    scatter_kernel<<<2048, 256>>>(adj_row, adj_col, adj_val, nnz, cursor, edges);

    int spmm_blocks = (n + 7) / 8;
    int samp_blocks = (2 * b + 7) / 8;
    float* out = (float*)d_out;
    size_t BD = (size_t)b * D;

    spmm_fused_kernel<<<spmm_blocks, 256>>>(rowrange, edges, h0, h1, n);
    spmm_fused_kernel<<<spmm_blocks, 256>>>(rowrange, edges, h1, h2, n);
    sampled_fused_kernel<<<samp_blocks, 256>>>(rowrange, edges, h1, h2,
        (const float2*)ue_on, (const float2*)ie_on,
        (const float2*)ue_tg, (const float2*)ie_tg,
        user_idx, item_idx,
        (float2*)S,
        (float2*)(out + BD),
        (float2*)(out + 3 * BD),
        b, uN);
    pred_kernel<<<(2 * b) / 4, dim3(64, 4)>>>(S, pred_w, pred_b,
        out, out + 2 * BD, b);
}

// round 6
// speedup vs baseline: 1.1941x; 1.1927x over previous
#include <cuda_runtime.h>
#include <cuda_fp16.h>

// ---------------------------------------------------------------------------
// BUIR / LightGCN forward, fp16-fused, 4-edges-in-flight SpMM.
//   - Online+target embeddings interleaved per node: H[r] = [64 on | 64 tg]
//     fp16 = 256B row. One SpMM pass computes BOTH encodings' layers.
//   - CSR by counting sort; single fused scan kernel (arrival-order bases).
//   - SpMM: warp per row; per inner step 4 edges in flight (each half-warp
//     issues TWO independent LDG.128 gathers) -> MLP ~4/warp. No unroll
//     pragmas (short dynamic loops schedule better unforced).
//   - Layer 3 only at sampled rows, fused with acc=(ego+X1+X2+X3)/4.
// Output layout: [u_pred | u_target | i_pred | i_target], each [B,64] f32.
// ---------------------------------------------------------------------------

#define D        64
#define HROW     64          // half2 per node row (128 halfs = 256B)
#define N_NODES  300000
#define NNZ_MAX  6400000
#define B_MAX    4096
#define HIST_BLOCKS 1024

// Scratch (device globals — no allocation allowed in kernel_launch)
__device__ int     g_counts[N_NODES];        // zero at load; re-zeroed each call
__device__ int2    g_rowrange[N_NODES];      // {start, end} per row
__device__ int     g_cursor[N_NODES];
__device__ int     g_scan_cursor;            // reset by hist kernel each call
__device__ int2    g_edges[NNZ_MAX];         // {col, val bits}, row-grouped
__device__ __half2 g_H0[(size_t)N_NODES * HROW];
__device__ __half2 g_H1[(size_t)N_NODES * HROW];
__device__ __half2 g_H2[(size_t)N_NODES * HROW];
__device__ float   g_S[(size_t)2 * B_MAX * D];

static __device__ __forceinline__ unsigned h2_as_u(__half2 h) {
    return *reinterpret_cast<unsigned*>(&h);
}
static __device__ __forceinline__ __half2 u_as_h2(unsigned u) {
    return *reinterpret_cast<__half2*>(&u);
}

// ---------------------------------------------------------------------------
// Fused: histogram (blocks [0,HIST_BLOCKS)) + ego->fp16 convert (rest).
// Also resets the scan cursor for the next launch.
// ---------------------------------------------------------------------------
__global__ void __launch_bounds__(256) hist_convert_kernel(
    const int* __restrict__ row, int nnz, int* __restrict__ counts,
    const float2* __restrict__ ue_on, const float2* __restrict__ ie_on,
    const float2* __restrict__ ue_tg, const float2* __restrict__ ie_tg,
    __half2* __restrict__ h0, int n, int usplit)
{
    if (blockIdx.x == 0 && threadIdx.x == 0) g_scan_cursor = 0;
    if (blockIdx.x < HIST_BLOCKS) {
        for (int i = blockIdx.x * 256 + threadIdx.x; i < nnz;
             i += HIST_BLOCKS * 256)
            atomicAdd(&counts[__ldcs(&row[i])], 1);   // return unused -> REDG
    } else {
        int idx = (blockIdx.x - HIST_BLOCKS) * 256 + threadIdx.x;
        if (idx >= n * 32) return;
        int r = idx >> 5;
        int k = idx & 31;
        float2 on, tg;
        if (r < usplit) {
            on = ue_on[(size_t)r * 32 + k];
            tg = ue_tg[(size_t)r * 32 + k];
        } else {
            on = ie_on[(size_t)(r - usplit) * 32 + k];
            tg = ie_tg[(size_t)(r - usplit) * 32 + k];
        }
        h0[(size_t)r * HROW + k]      = __floats2half2_rn(on.x, on.y);
        h0[(size_t)r * HROW + 32 + k] = __floats2half2_rn(tg.x, tg.y);
    }
}

// ---------------------------------------------------------------------------
// Single-kernel scan: block-local inclusive scan; block base claimed by
// arrival-order atomicAdd (valid because CSR ranges need not be row-ordered).
// Emits rowrange + cursor, re-zeroes counts for the next call.
// ---------------------------------------------------------------------------
__global__ void scan_fused_kernel(int* __restrict__ counts, int n,
                                  int2* __restrict__ rowrange,
                                  int* __restrict__ cursor) {
    __shared__ int sd[1024];
    __shared__ int sbase;
    int tid = threadIdx.x;
    int i = blockIdx.x * 1024 + tid;
    int v = (i < n) ? counts[i] : 0;
    sd[tid] = v;
    __syncthreads();
    #pragma unroll
    for (int off = 1; off < 1024; off <<= 1) {
        int t = (tid >= off) ? sd[tid - off] : 0;
        __syncthreads();
        sd[tid] += t;
        __syncthreads();
    }
    if (tid == 1023) sbase = atomicAdd(&g_scan_cursor, sd[1023]);
    __syncthreads();
    if (i < n) {
        int start = sbase + sd[tid] - v;
        rowrange[i] = make_int2(start, start + v);
        cursor[i]   = start;
        counts[i]   = 0;
    }
}

// ---------------------------------------------------------------------------
// Scatter: position via per-row cursor atomics.
// ---------------------------------------------------------------------------
__global__ void scatter_kernel(const int* __restrict__ row, const int* __restrict__ col,
                               const float* __restrict__ val, int nnz,
                               int* __restrict__ cursor, int2* __restrict__ edges) {
    for (int i = blockIdx.x * blockDim.x + threadIdx.x; i < nnz;
         i += gridDim.x * blockDim.x) {
        int r = __ldcs(&row[i]);
        int pos = atomicAdd(&cursor[r], 1);
        __stcs(&edges[pos], make_int2(__ldcs(&col[i]),
                                      __float_as_int(__ldcs(&val[i]))));
    }
}

// ---------------------------------------------------------------------------
// Fused SpMM: warp per row. Inner step = 4 edges: half-warp h takes edges
// j+h and j+2+h, each lane issuing TWO independent LDG.128 gathers (16B
// segment hl of the 256B source row). Pad lanes carry ev=(0,0): v=0 keeps
// the FMA exact and the pad gather hits node 0's row (L1-hot).
// Partials combined with shfl_xor(16); lanes 0-15 store uint4.
// ---------------------------------------------------------------------------
__global__ void __launch_bounds__(256) spmm_fused_kernel(
    const int2* __restrict__ rowrange, const int2* __restrict__ edges,
    const __half2* __restrict__ xin, __half2* __restrict__ xout, int nrows)
{
    int w = (blockIdx.x * 256 + threadIdx.x) >> 5;
    if (w >= nrows) return;
    int lane = threadIdx.x & 31;
    int half = lane >> 4;          // which edge of the pair
    int hl   = lane & 15;          // 16B segment index within the row
    int2 rr = __ldg(&rowrange[w]);
    int start = rr.x;
    int end   = rr.y;

    float2 acc[4];
    #pragma unroll
    for (int k = 0; k < 4; k++) acc[k] = make_float2(0.f, 0.f);

    const char* xbase = (const char*)xin;

    for (int base = start; base < end; base += 32) {
        int2 ev = make_int2(0, 0);                 // pad: col 0 / val 0
        if (base + lane < end) ev = __ldcs(&edges[base + lane]);
        int cnt = min(32, end - base);
        for (int j = 0; j < cnt; j += 4) {
            int sA = j + half;                     // edge A for this half-warp
            int sB = j + 2 + half;                 // edge B (may be pad)
            int   cA = __shfl_sync(0xffffffffu, ev.x, sA);
            float vA = __int_as_float(__shfl_sync(0xffffffffu, ev.y, sA));
            int   cB = __shfl_sync(0xffffffffu, ev.x, sB);
            float vB = __int_as_float(__shfl_sync(0xffffffffu, ev.y, sB));
            uint4 rA = __ldg((const uint4*)(xbase + (size_t)cA * 256 + hl * 16));
            uint4 rB = __ldg((const uint4*)(xbase + (size_t)cB * 256 + hl * 16));

            float2 a0 = __half22float2(u_as_h2(rA.x));
            float2 a1 = __half22float2(u_as_h2(rA.y));
            float2 a2 = __half22float2(u_as_h2(rA.z));
            float2 a3 = __half22float2(u_as_h2(rA.w));
            acc[0].x = fmaf(vA, a0.x, acc[0].x);
            acc[0].y = fmaf(vA, a0.y, acc[0].y);
            acc[1].x = fmaf(vA, a1.x, acc[1].x);
            acc[1].y = fmaf(vA, a1.y, acc[1].y);
            acc[2].x = fmaf(vA, a2.x, acc[2].x);
            acc[2].y = fmaf(vA, a2.y, acc[2].y);
            acc[3].x = fmaf(vA, a3.x, acc[3].x);
            acc[3].y = fmaf(vA, a3.y, acc[3].y);

            float2 b0 = __half22float2(u_as_h2(rB.x));
            float2 b1 = __half22float2(u_as_h2(rB.y));
            float2 b2 = __half22float2(u_as_h2(rB.z));
            float2 b3 = __half22float2(u_as_h2(rB.w));
            acc[0].x = fmaf(vB, b0.x, acc[0].x);
            acc[0].y = fmaf(vB, b0.y, acc[0].y);
            acc[1].x = fmaf(vB, b1.x, acc[1].x);
            acc[1].y = fmaf(vB, b1.y, acc[1].y);
            acc[2].x = fmaf(vB, b2.x, acc[2].x);
            acc[2].y = fmaf(vB, b2.y, acc[2].y);
            acc[3].x = fmaf(vB, b3.x, acc[3].x);
            acc[3].y = fmaf(vB, b3.y, acc[3].y);
        }
    }

    #pragma unroll
    for (int k = 0; k < 4; k++) {
        acc[k].x += __shfl_xor_sync(0xffffffffu, acc[k].x, 16);
        acc[k].y += __shfl_xor_sync(0xffffffffu, acc[k].y, 16);
    }
    if (lane < 16) {
        uint4 o;
        o.x = h2_as_u(__floats2half2_rn(acc[0].x, acc[0].y));
        o.y = h2_as_u(__floats2half2_rn(acc[1].x, acc[1].y));
        o.z = h2_as_u(__floats2half2_rn(acc[2].x, acc[2].y));
        o.w = h2_as_u(__floats2half2_rn(acc[3].x, acc[3].y));
        __stcs((uint4*)((char*)xout + (size_t)w * 256 + hl * 16), o);
    }
}

// ---------------------------------------------------------------------------
// Layer-3 at sampled rows (both encodings), fused with
// acc = 0.25*(ego_fp32 + X1 + X2 + X3). Online acc -> S, target acc -> out.
// ---------------------------------------------------------------------------
__global__ void __launch_bounds__(256) sampled_fused_kernel(
    const int2* __restrict__ rowrange, const int2* __restrict__ edges,
    const __half2* __restrict__ h1, const __half2* __restrict__ h2,
    const float2* __restrict__ ue_on, const float2* __restrict__ ie_on,
    const float2* __restrict__ ue_tg, const float2* __restrict__ ie_tg,
    const int* __restrict__ user_idx, const int* __restrict__ item_idx,
    float2* __restrict__ s_on,
    float2* __restrict__ out_utg, float2* __restrict__ out_itg,
    int b, int usplit)
{
    int s = (blockIdx.x * 256 + threadIdx.x) >> 5;
    if (s >= 2 * b) return;
    int lane = threadIdx.x & 31;
    int r = (s < b) ? __ldg(&user_idx[s]) : usplit + __ldg(&item_idx[s - b]);

    int2 rr = __ldg(&rowrange[r]);
    int start = rr.x;
    int end   = rr.y;
    float2 aon = make_float2(0.f, 0.f);
    float2 atg = make_float2(0.f, 0.f);
    for (int base = start; base < end; base += 32) {
        int2 ev = make_int2(0, 0);
        if (base + lane < end) ev = edges[base + lane];
        int cnt = min(32, end - base);
        for (int j = 0; j < cnt; j++) {
            int   c = __shfl_sync(0xffffffffu, ev.x, j);
            float v = __int_as_float(__shfl_sync(0xffffffffu, ev.y, j));
            const __half2* src = h2 + (size_t)c * HROW;
            float2 a = __half22float2(__ldg(src + lane));
            float2 t = __half22float2(__ldg(src + 32 + lane));
            aon.x = fmaf(v, a.x, aon.x);
            aon.y = fmaf(v, a.y, aon.y);
            atg.x = fmaf(v, t.x, atg.x);
            atg.y = fmaf(v, t.y, atg.y);
        }
    }

    float2 e_on = (r < usplit) ? __ldg(&ue_on[(size_t)r * 32 + lane])
                               : __ldg(&ie_on[(size_t)(r - usplit) * 32 + lane]);
    float2 e_tg = (r < usplit) ? __ldg(&ue_tg[(size_t)r * 32 + lane])
                               : __ldg(&ie_tg[(size_t)(r - usplit) * 32 + lane]);
    float2 x1on = __half22float2(__ldg(h1 + (size_t)r * HROW + lane));
    float2 x1tg = __half22float2(__ldg(h1 + (size_t)r * HROW + 32 + lane));
    float2 x2on = __half22float2(__ldg(h2 + (size_t)r * HROW + lane));
    float2 x2tg = __half22float2(__ldg(h2 + (size_t)r * HROW + 32 + lane));

    float2 ron, rtg;
    ron.x = 0.25f * (e_on.x + x1on.x + x2on.x + aon.x);
    ron.y = 0.25f * (e_on.y + x1on.y + x2on.y + aon.y);
    rtg.x = 0.25f * (e_tg.x + x1tg.x + x2tg.x + atg.x);
    rtg.y = 0.25f * (e_tg.y + x1tg.y + x2tg.y + atg.y);

    s_on[(size_t)s * 32 + lane] = ron;
    float2* dtg = (s < b) ? (out_utg + (size_t)s * 32 + lane)
                          : (out_itg + (size_t)(s - b) * 32 + lane);
    *dtg = rtg;
}

// ---------------------------------------------------------------------------
// Linear head: out = S @ W^T + bias   (S: [2B,64], W: [64,64] row-major)
// ---------------------------------------------------------------------------
__global__ void __launch_bounds__(256) pred_kernel(
    const float* __restrict__ S, const float* __restrict__ W,
    const float* __restrict__ bias,
    float* __restrict__ out_u, float* __restrict__ out_i, int b)
{
    __shared__ float Wt[64][65];
    __shared__ float srow[4][64];
    __shared__ float sb[64];
    int tx = threadIdx.x, ty = threadIdx.y;
    int tid = ty * 64 + tx;
    for (int idx = tid; idx < 4096; idx += 256)
        Wt[idx & 63][idx >> 6] = W[idx];
    if (tid < 64) sb[tid] = bias[tid];
    int s = blockIdx.x * 4 + ty;
    srow[ty][tx] = S[(size_t)s * 64 + tx];
    __syncthreads();

    float acc = sb[tx];
    #pragma unroll
    for (int k = 0; k < 64; k++)
        acc = fmaf(srow[ty][k], Wt[k][tx], acc);

    float* d = (s < b) ? (out_u + (size_t)s * 64 + tx)
                       : (out_i + (size_t)(s - b) * 64 + tx);
    *d = acc;
}

// ---------------------------------------------------------------------------
// Launch
// ---------------------------------------------------------------------------
extern "C" void kernel_launch(void* const* d_in, const int* in_sizes, int n_in,
                              void* d_out, int out_size) {
    const float* ue_on   = (const float*)d_in[0];
    const float* ie_on   = (const float*)d_in[1];
    const float* ue_tg   = (const float*)d_in[2];
    const float* ie_tg   = (const float*)d_in[3];
    const float* adj_val = (const float*)d_in[4];
    const float* pred_w  = (const float*)d_in[5];
    const float* pred_b  = (const float*)d_in[6];
    const int*   adj_row = (const int*)d_in[7];
    const int*   adj_col = (const int*)d_in[8];
    const int*   user_idx = (const int*)d_in[9];
    const int*   item_idx = (const int*)d_in[10];

    int uN  = in_sizes[0] / D;
    int iN  = in_sizes[1] / D;
    int n   = uN + iN;
    int nnz = in_sizes[4];
    int b   = in_sizes[9];

    int *counts, *cursor;
    int2 *rowrange, *edges;
    __half2 *h0, *h1, *h2;
    float* S;
    cudaGetSymbolAddress((void**)&counts,   g_counts);
    cudaGetSymbolAddress((void**)&rowrange, g_rowrange);
    cudaGetSymbolAddress((void**)&cursor,   g_cursor);
    cudaGetSymbolAddress((void**)&edges,    g_edges);
    cudaGetSymbolAddress((void**)&h0,       g_H0);
    cudaGetSymbolAddress((void**)&h1,       g_H1);
    cudaGetSymbolAddress((void**)&h2,       g_H2);
    cudaGetSymbolAddress((void**)&S,        g_S);

    // --- CSR build (counts pre-zeroed by previous call / module load) ---
    int conv_blocks = (n * 32 + 255) / 256;
    hist_convert_kernel<<<HIST_BLOCKS + conv_blocks, 256>>>(
        adj_row, nnz, counts,
        (const float2*)ue_on, (const float2*)ie_on,
        (const float2*)ue_tg, (const float2*)ie_tg, h0, n, uN);
    int nb = (n + 1023) / 1024;
    scan_fused_kernel<<<nb, 1024>>>(counts, n, rowrange, cursor);
    scatter_kernel<<<2048, 256>>>(adj_row, adj_col, adj_val, nnz, cursor, edges);

    int spmm_blocks = (n + 7) / 8;
    int samp_blocks = (2 * b + 7) / 8;
    float* out = (float*)d_out;
    size_t BD = (size_t)b * D;

    spmm_fused_kernel<<<spmm_blocks, 256>>>(rowrange, edges, h0, h1, n);
    spmm_fused_kernel<<<spmm_blocks, 256>>>(rowrange, edges, h1, h2, n);
    sampled_fused_kernel<<<samp_blocks, 256>>>(rowrange, edges, h1, h2,
        (const float2*)ue_on, (const float2*)ie_on,
        (const float2*)ue_tg, (const float2*)ie_tg,
        user_idx, item_idx,
        (float2*)S,
        (float2*)(out + BD),
        (float2*)(out + 3 * BD),
        b, uN);
    pred_kernel<<<(2 * b) / 4, dim3(64, 4)>>>(S, pred_w, pred_b,
        out, out + 2 * BD, b);
}

// round 7
// speedup vs baseline: 1.2388x; 1.0375x over previous
#include <cuda_runtime.h>
#include <cuda_fp16.h>

// ---------------------------------------------------------------------------
// BUIR / LightGCN forward, fp16-fused, 8-edges-in-flight SpMM.
//   - Online+target embeddings interleaved per node: H[r] = [64 on | 64 tg]
//     fp16 = 256B row. One SpMM pass computes BOTH encodings' layers.
//   - CSR by counting sort; single fused scan kernel (arrival-order bases).
//   - SpMM: warp per row; per inner step 8 edges in flight (each half-warp
//     issues FOUR independent LDG.128 gathers) -> MLP ~8/warp.
//   - Layer 3 only at sampled rows, fused with acc=(ego+X1+X2+X3)/4.
// Output layout: [u_pred | u_target | i_pred | i_target], each [B,64] f32.
// ---------------------------------------------------------------------------

#define D        64
#define HROW     64          // half2 per node row (128 halfs = 256B)
#define N_NODES  300000
#define NNZ_MAX  6400000
#define B_MAX    4096
#define HIST_BLOCKS 1024

// Scratch (device globals — no allocation allowed in kernel_launch)
__device__ int     g_counts[N_NODES];        // zero at load; re-zeroed each call
__device__ int2    g_rowrange[N_NODES];      // {start, end} per row
__device__ int     g_cursor[N_NODES];
__device__ int     g_scan_cursor;            // reset by hist kernel each call
__device__ int2    g_edges[NNZ_MAX];         // {col, val bits}, row-grouped
__device__ __half2 g_H0[(size_t)N_NODES * HROW];
__device__ __half2 g_H1[(size_t)N_NODES * HROW];
__device__ __half2 g_H2[(size_t)N_NODES * HROW];
__device__ float   g_S[(size_t)2 * B_MAX * D];

static __device__ __forceinline__ unsigned h2_as_u(__half2 h) {
    return *reinterpret_cast<unsigned*>(&h);
}
static __device__ __forceinline__ __half2 u_as_h2(unsigned u) {
    return *reinterpret_cast<__half2*>(&u);
}

// ---------------------------------------------------------------------------
// Fused: histogram (blocks [0,HIST_BLOCKS)) + ego->fp16 convert (rest).
// Also resets the scan cursor for the next launch.
// ---------------------------------------------------------------------------
__global__ void __launch_bounds__(256) hist_convert_kernel(
    const int* __restrict__ row, int nnz, int* __restrict__ counts,
    const float2* __restrict__ ue_on, const float2* __restrict__ ie_on,
    const float2* __restrict__ ue_tg, const float2* __restrict__ ie_tg,
    __half2* __restrict__ h0, int n, int usplit)
{
    if (blockIdx.x == 0 && threadIdx.x == 0) g_scan_cursor = 0;
    if (blockIdx.x < HIST_BLOCKS) {
        for (int i = blockIdx.x * 256 + threadIdx.x; i < nnz;
             i += HIST_BLOCKS * 256)
            atomicAdd(&counts[__ldcs(&row[i])], 1);   // return unused -> REDG
    } else {
        int idx = (blockIdx.x - HIST_BLOCKS) * 256 + threadIdx.x;
        if (idx >= n * 32) return;
        int r = idx >> 5;
        int k = idx & 31;
        float2 on, tg;
        if (r < usplit) {
            on = ue_on[(size_t)r * 32 + k];
            tg = ue_tg[(size_t)r * 32 + k];
        } else {
            on = ie_on[(size_t)(r - usplit) * 32 + k];
            tg = ie_tg[(size_t)(r - usplit) * 32 + k];
        }
        h0[(size_t)r * HROW + k]      = __floats2half2_rn(on.x, on.y);
        h0[(size_t)r * HROW + 32 + k] = __floats2half2_rn(tg.x, tg.y);
    }
}

// ---------------------------------------------------------------------------
// Single-kernel scan: block-local inclusive scan; block base claimed by
// arrival-order atomicAdd (valid because CSR ranges need not be row-ordered).
// Emits rowrange + cursor, re-zeroes counts for the next call.
// ---------------------------------------------------------------------------
__global__ void scan_fused_kernel(int* __restrict__ counts, int n,
                                  int2* __restrict__ rowrange,
                                  int* __restrict__ cursor) {
    __shared__ int sd[1024];
    __shared__ int sbase;
    int tid = threadIdx.x;
    int i = blockIdx.x * 1024 + tid;
    int v = (i < n) ? counts[i] : 0;
    sd[tid] = v;
    __syncthreads();
    #pragma unroll
    for (int off = 1; off < 1024; off <<= 1) {
        int t = (tid >= off) ? sd[tid - off] : 0;
        __syncthreads();
        sd[tid] += t;
        __syncthreads();
    }
    if (tid == 1023) sbase = atomicAdd(&g_scan_cursor, sd[1023]);
    __syncthreads();
    if (i < n) {
        int start = sbase + sd[tid] - v;
        rowrange[i] = make_int2(start, start + v);
        cursor[i]   = start;
        counts[i]   = 0;
    }
}

// ---------------------------------------------------------------------------
// Scatter: position via per-row cursor atomics.
// ---------------------------------------------------------------------------
__global__ void scatter_kernel(const int* __restrict__ row, const int* __restrict__ col,
                               const float* __restrict__ val, int nnz,
                               int* __restrict__ cursor, int2* __restrict__ edges) {
    for (int i = blockIdx.x * blockDim.x + threadIdx.x; i < nnz;
         i += gridDim.x * blockDim.x) {
        int r = __ldcs(&row[i]);
        int pos = atomicAdd(&cursor[r], 1);
        __stcs(&edges[pos], make_int2(__ldcs(&col[i]),
                                      __float_as_int(__ldcs(&val[i]))));
    }
}

// ---------------------------------------------------------------------------
// Fused SpMM: warp per row. Inner step = 8 edges: half-warp h takes edges
// j+h, j+2+h, j+4+h, j+6+h; each lane issues FOUR independent LDG.128
// gathers (16B segment hl of the 256B source row). Pad lanes carry
// ev=(0,0): v=0 keeps the FMA exact and pad gathers hit node 0 (L1-hot).
// Partials combined with shfl_xor(16); lanes 0-15 store uint4.
// ---------------------------------------------------------------------------
__global__ void __launch_bounds__(256) spmm_fused_kernel(
    const int2* __restrict__ rowrange, const int2* __restrict__ edges,
    const __half2* __restrict__ xin, __half2* __restrict__ xout, int nrows)
{
    int w = (blockIdx.x * 256 + threadIdx.x) >> 5;
    if (w >= nrows) return;
    int lane = threadIdx.x & 31;
    int half = lane >> 4;          // which edge slot within a pair
    int hl   = lane & 15;          // 16B segment index within the row
    int2 rr = __ldg(&rowrange[w]);
    int start = rr.x;
    int end   = rr.y;

    float2 acc[4];
    #pragma unroll
    for (int k = 0; k < 4; k++) acc[k] = make_float2(0.f, 0.f);

    const char* xbase = (const char*)xin;

    for (int base = start; base < end; base += 32) {
        int2 ev = make_int2(0, 0);                 // pad: col 0 / val 0
        if (base + lane < end) ev = __ldcs(&edges[base + lane]);
        int cnt = min(32, end - base);
        for (int j = 0; j < cnt; j += 8) {
            int   cA = __shfl_sync(0xffffffffu, ev.x, j + half);
            float vA = __int_as_float(__shfl_sync(0xffffffffu, ev.y, j + half));
            int   cB = __shfl_sync(0xffffffffu, ev.x, j + 2 + half);
            float vB = __int_as_float(__shfl_sync(0xffffffffu, ev.y, j + 2 + half));
            int   cC = __shfl_sync(0xffffffffu, ev.x, j + 4 + half);
            float vC = __int_as_float(__shfl_sync(0xffffffffu, ev.y, j + 4 + half));
            int   cD = __shfl_sync(0xffffffffu, ev.x, j + 6 + half);
            float vD = __int_as_float(__shfl_sync(0xffffffffu, ev.y, j + 6 + half));

            uint4 rA = __ldg((const uint4*)(xbase + (size_t)cA * 256 + hl * 16));
            uint4 rB = __ldg((const uint4*)(xbase + (size_t)cB * 256 + hl * 16));
            uint4 rC = __ldg((const uint4*)(xbase + (size_t)cC * 256 + hl * 16));
            uint4 rD = __ldg((const uint4*)(xbase + (size_t)cD * 256 + hl * 16));

            float2 t;
            t = __half22float2(u_as_h2(rA.x)); acc[0].x = fmaf(vA, t.x, acc[0].x); acc[0].y = fmaf(vA, t.y, acc[0].y);
            t = __half22float2(u_as_h2(rA.y)); acc[1].x = fmaf(vA, t.x, acc[1].x); acc[1].y = fmaf(vA, t.y, acc[1].y);
            t = __half22float2(u_as_h2(rA.z)); acc[2].x = fmaf(vA, t.x, acc[2].x); acc[2].y = fmaf(vA, t.y, acc[2].y);
            t = __half22float2(u_as_h2(rA.w)); acc[3].x = fmaf(vA, t.x, acc[3].x); acc[3].y = fmaf(vA, t.y, acc[3].y);

            t = __half22float2(u_as_h2(rB.x)); acc[0].x = fmaf(vB, t.x, acc[0].x); acc[0].y = fmaf(vB, t.y, acc[0].y);
            t = __half22float2(u_as_h2(rB.y)); acc[1].x = fmaf(vB, t.x, acc[1].x); acc[1].y = fmaf(vB, t.y, acc[1].y);
            t = __half22float2(u_as_h2(rB.z)); acc[2].x = fmaf(vB, t.x, acc[2].x); acc[2].y = fmaf(vB, t.y, acc[2].y);
            t = __half22float2(u_as_h2(rB.w)); acc[3].x = fmaf(vB, t.x, acc[3].x); acc[3].y = fmaf(vB, t.y, acc[3].y);

            t = __half22float2(u_as_h2(rC.x)); acc[0].x = fmaf(vC, t.x, acc[0].x); acc[0].y = fmaf(vC, t.y, acc[0].y);
            t = __half22float2(u_as_h2(rC.y)); acc[1].x = fmaf(vC, t.x, acc[1].x); acc[1].y = fmaf(vC, t.y, acc[1].y);
            t = __half22float2(u_as_h2(rC.z)); acc[2].x = fmaf(vC, t.x, acc[2].x); acc[2].y = fmaf(vC, t.y, acc[2].y);
            t = __half22float2(u_as_h2(rC.w)); acc[3].x = fmaf(vC, t.x, acc[3].x); acc[3].y = fmaf(vC, t.y, acc[3].y);

            t = __half22float2(u_as_h2(rD.x)); acc[0].x = fmaf(vD, t.x, acc[0].x); acc[0].y = fmaf(vD, t.y, acc[0].y);
            t = __half22float2(u_as_h2(rD.y)); acc[1].x = fmaf(vD, t.x, acc[1].x); acc[1].y = fmaf(vD, t.y, acc[1].y);
            t = __half22float2(u_as_h2(rD.z)); acc[2].x = fmaf(vD, t.x, acc[2].x); acc[2].y = fmaf(vD, t.y, acc[2].y);
            t = __half22float2(u_as_h2(rD.w)); acc[3].x = fmaf(vD, t.x, acc[3].x); acc[3].y = fmaf(vD, t.y, acc[3].y);
        }
    }

    #pragma unroll
    for (int k = 0; k < 4; k++) {
        acc[k].x += __shfl_xor_sync(0xffffffffu, acc[k].x, 16);
        acc[k].y += __shfl_xor_sync(0xffffffffu, acc[k].y, 16);
    }
    if (lane < 16) {
        uint4 o;
        o.x = h2_as_u(__floats2half2_rn(acc[0].x, acc[0].y));
        o.y = h2_as_u(__floats2half2_rn(acc[1].x, acc[1].y));
        o.z = h2_as_u(__floats2half2_rn(acc[2].x, acc[2].y));
        o.w = h2_as_u(__floats2half2_rn(acc[3].x, acc[3].y));
        __stcs((uint4*)((char*)xout + (size_t)w * 256 + hl * 16), o);
    }
}

// ---------------------------------------------------------------------------
// Layer-3 at sampled rows (both encodings), fused with
// acc = 0.25*(ego_fp32 + X1 + X2 + X3). Online acc -> S, target acc -> out.
// ---------------------------------------------------------------------------
__global__ void __launch_bounds__(256) sampled_fused_kernel(
    const int2* __restrict__ rowrange, const int2* __restrict__ edges,
    const __half2* __restrict__ h1, const __half2* __restrict__ h2,
    const float2* __restrict__ ue_on, const float2* __restrict__ ie_on,
    const float2* __restrict__ ue_tg, const float2* __restrict__ ie_tg,
    const int* __restrict__ user_idx, const int* __restrict__ item_idx,
    float2* __restrict__ s_on,
    float2* __restrict__ out_utg, float2* __restrict__ out_itg,
    int b, int usplit)
{
    int s = (blockIdx.x * 256 + threadIdx.x) >> 5;
    if (s >= 2 * b) return;
    int lane = threadIdx.x & 31;
    int r = (s < b) ? __ldg(&user_idx[s]) : usplit + __ldg(&item_idx[s - b]);

    int2 rr = __ldg(&rowrange[r]);
    int start = rr.x;
    int end   = rr.y;
    float2 aon = make_float2(0.f, 0.f);
    float2 atg = make_float2(0.f, 0.f);
    for (int base = start; base < end; base += 32) {
        int2 ev = make_int2(0, 0);
        if (base + lane < end) ev = edges[base + lane];
        int cnt = min(32, end - base);
        for (int j = 0; j < cnt; j += 2) {
            int jA = j, jB = j + 1;
            int   cA = __shfl_sync(0xffffffffu, ev.x, jA);
            float vA = __int_as_float(__shfl_sync(0xffffffffu, ev.y, jA));
            int   cB = __shfl_sync(0xffffffffu, ev.x, jB);
            float vB = __int_as_float(__shfl_sync(0xffffffffu, ev.y, jB));
            const __half2* sA = h2 + (size_t)cA * HROW;
            const __half2* sB = h2 + (size_t)cB * HROW;
            float2 a  = __half22float2(__ldg(sA + lane));
            float2 t  = __half22float2(__ldg(sA + 32 + lane));
            float2 a2 = __half22float2(__ldg(sB + lane));
            float2 t2 = __half22float2(__ldg(sB + 32 + lane));
            aon.x = fmaf(vA, a.x, aon.x);
            aon.y = fmaf(vA, a.y, aon.y);
            atg.x = fmaf(vA, t.x, atg.x);
            atg.y = fmaf(vA, t.y, atg.y);
            aon.x = fmaf(vB, a2.x, aon.x);
            aon.y = fmaf(vB, a2.y, aon.y);
            atg.x = fmaf(vB, t2.x, atg.x);
            atg.y = fmaf(vB, t2.y, atg.y);
        }
    }

    float2 e_on = (r < usplit) ? __ldg(&ue_on[(size_t)r * 32 + lane])
                               : __ldg(&ie_on[(size_t)(r - usplit) * 32 + lane]);
    float2 e_tg = (r < usplit) ? __ldg(&ue_tg[(size_t)r * 32 + lane])
                               : __ldg(&ie_tg[(size_t)(r - usplit) * 32 + lane]);
    float2 x1on = __half22float2(__ldg(h1 + (size_t)r * HROW + lane));
    float2 x1tg = __half22float2(__ldg(h1 + (size_t)r * HROW + 32 + lane));
    float2 x2on = __half22float2(__ldg(h2 + (size_t)r * HROW + lane));
    float2 x2tg = __half22float2(__ldg(h2 + (size_t)r * HROW + 32 + lane));

    float2 ron, rtg;
    ron.x = 0.25f * (e_on.x + x1on.x + x2on.x + aon.x);
    ron.y = 0.25f * (e_on.y + x1on.y + x2on.y + aon.y);
    rtg.x = 0.25f * (e_tg.x + x1tg.x + x2tg.x + atg.x);
    rtg.y = 0.25f * (e_tg.y + x1tg.y + x2tg.y + atg.y);

    s_on[(size_t)s * 32 + lane] = ron;
    float2* dtg = (s < b) ? (out_utg + (size_t)s * 32 + lane)
                          : (out_itg + (size_t)(s - b) * 32 + lane);
    *dtg = rtg;
}

// ---------------------------------------------------------------------------
// Linear head: out = S @ W^T + bias   (S: [2B,64], W: [64,64] row-major)
// ---------------------------------------------------------------------------
__global__ void __launch_bounds__(256) pred_kernel(
    const float* __restrict__ S, const float* __restrict__ W,
    const float* __restrict__ bias,
    float* __restrict__ out_u, float* __restrict__ out_i, int b)
{
    __shared__ float Wt[64][65];
    __shared__ float srow[4][64];
    __shared__ float sb[64];
    int tx = threadIdx.x, ty = threadIdx.y;
    int tid = ty * 64 + tx;
    for (int idx = tid; idx < 4096; idx += 256)
        Wt[idx & 63][idx >> 6] = W[idx];
    if (tid < 64) sb[tid] = bias[tid];
    int s = blockIdx.x * 4 + ty;
    srow[ty][tx] = S[(size_t)s * 64 + tx];
    __syncthreads();

    float acc = sb[tx];
    #pragma unroll
    for (int k = 0; k < 64; k++)
        acc = fmaf(srow[ty][k], Wt[k][tx], acc);

    float* d = (s < b) ? (out_u + (size_t)s * 64 + tx)
                       : (out_i + (size_t)(s - b) * 64 + tx);
    *d = acc;
}

// ---------------------------------------------------------------------------
// Launch
// ---------------------------------------------------------------------------
extern "C" void kernel_launch(void* const* d_in, const int* in_sizes, int n_in,
                              void* d_out, int out_size) {
    const float* ue_on   = (const float*)d_in[0];
    const float* ie_on   = (const float*)d_in[1];
    const float* ue_tg   = (const float*)d_in[2];
    const float* ie_tg   = (const float*)d_in[3];
    const float* adj_val = (const float*)d_in[4];
    const float* pred_w  = (const float*)d_in[5];
    const float* pred_b  = (const float*)d_in[6];
    const int*   adj_row = (const int*)d_in[7];
    const int*   adj_col = (const int*)d_in[8];
    const int*   user_idx = (const int*)d_in[9];
    const int*   item_idx = (const int*)d_in[10];

    int uN  = in_sizes[0] / D;
    int iN  = in_sizes[1] / D;
    int n   = uN + iN;
    int nnz = in_sizes[4];
    int b   = in_sizes[9];

    int *counts, *cursor;
    int2 *rowrange, *edges;
    __half2 *h0, *h1, *h2;
    float* S;
    cudaGetSymbolAddress((void**)&counts,   g_counts);
    cudaGetSymbolAddress((void**)&rowrange, g_rowrange);
    cudaGetSymbolAddress((void**)&cursor,   g_cursor);
    cudaGetSymbolAddress((void**)&edges,    g_edges);
    cudaGetSymbolAddress((void**)&h0,       g_H0);
    cudaGetSymbolAddress((void**)&h1,       g_H1);
    cudaGetSymbolAddress((void**)&h2,       g_H2);
    cudaGetSymbolAddress((void**)&S,        g_S);

    // --- CSR build (counts pre-zeroed by previous call / module load) ---
    int conv_blocks = (n * 32 + 255) / 256;
    hist_convert_kernel<<<HIST_BLOCKS + conv_blocks, 256>>>(
        adj_row, nnz, counts,
        (const float2*)ue_on, (const float2*)ie_on,
        (const float2*)ue_tg, (const float2*)ie_tg, h0, n, uN);
    int nb = (n + 1023) / 1024;
    scan_fused_kernel<<<nb, 1024>>>(counts, n, rowrange, cursor);
    scatter_kernel<<<2048, 256>>>(adj_row, adj_col, adj_val, nnz, cursor, edges);

    int spmm_blocks = (n + 7) / 8;
    int samp_blocks = (2 * b + 7) / 8;
    float* out = (float*)d_out;
    size_t BD = (size_t)b * D;

    spmm_fused_kernel<<<spmm_blocks, 256>>>(rowrange, edges, h0, h1, n);
    spmm_fused_kernel<<<spmm_blocks, 256>>>(rowrange, edges, h1, h2, n);
    sampled_fused_kernel<<<samp_blocks, 256>>>(rowrange, edges, h1, h2,
        (const float2*)ue_on, (const float2*)ie_on,
        (const float2*)ue_tg, (const float2*)ie_tg,
        user_idx, item_idx,
        (float2*)S,
        (float2*)(out + BD),
        (float2*)(out + 3 * BD),
        b, uN);
    pred_kernel<<<(2 * b) / 4, dim3(64, 4)>>>(S, pred_w, pred_b,
        out, out + 2 * BD, b);
}